// round 8
// baseline (speedup 1.0000x reference)
#include <cuda_runtime.h>
#include <cstdint>

// ============================================================
// out[8192,4096] = x @ W^T + b + 2*((x @ A^T) @ B^T)
// Folded: Weff = W + 2*(B@A);  out = x @ Weff^T + b  (tf32 mma.sync)
// R8: 512 threads (16 warps, 4/SMSP) for latency hiding;
//     roundx fused into mainloop (cvt.rna on A fragments);
//     no manual fragment double-buffer.
// ============================================================

#define M_DIM 8192
#define N_DIM 4096
#define K_DIM 4096

#define BM 128
#define BN 256
#define BK 32
#define NK (K_DIM / BK)        // 128
#define NTHREADS 512

// padded smem rows: 32 tf32 + 4 pad = 36 words = 144B (16B multiple)
#define PAD_K 36
#define A_STAGE_W (BM * PAD_K)             // 4608 words
#define B_STAGE_W (BN * PAD_K)             // 9216 words
#define STAGE_W   (A_STAGE_W + B_STAGE_W)  // 13824 words = 55296 B
#define SMEM_TOTAL (4 * STAGE_W * 4)       // 221184 B

// scratch (static device global — no runtime allocation)
__device__ __align__(16) float g_Weff[(size_t)N_DIM * K_DIM];

// ---------------- PTX helpers ----------------
__device__ __forceinline__ uint32_t smem_u32(const void* p) {
    uint32_t a;
    asm("{ .reg .u64 t; cvta.to.shared.u64 t, %1; cvt.u32.u64 %0, t; }" : "=r"(a) : "l"(p));
    return a;
}

#define CP_ASYNC16(dst, src) \
    asm volatile("cp.async.cg.shared.global [%0], [%1], 16;" :: "r"(dst), "l"(src) : "memory")
#define CP_COMMIT() asm volatile("cp.async.commit_group;" ::: "memory")
#define CP_WAIT(n)  asm volatile("cp.async.wait_group %0;" :: "n"(n) : "memory")

__device__ __forceinline__ uint32_t f2tf32(float v) {
    uint32_t r;
    asm("cvt.rna.tf32.f32 %0, %1;" : "=r"(r) : "f"(v));
    return r;
}

__device__ __forceinline__ void mma_tf32(float c[4], const uint32_t a[4], const uint32_t b[2]) {
    asm volatile(
        "mma.sync.aligned.m16n8k8.row.col.f32.tf32.tf32.f32 "
        "{%0,%1,%2,%3}, {%4,%5,%6,%7}, {%8,%9}, {%0,%1,%2,%3};\n"
        : "+f"(c[0]), "+f"(c[1]), "+f"(c[2]), "+f"(c[3])
        : "r"(a[0]), "r"(a[1]), "r"(a[2]), "r"(a[3]), "r"(b[0]), "r"(b[1]));
}

// ---------------- prep kernel ----------------
// Weff[o,i] = round_tf32( W[o,i] + 2 * sum_r B[o,r] * A[r,i] )
__global__ __launch_bounds__(256) void weff_kernel(const float* __restrict__ W,
                                                   const float* __restrict__ A,
                                                   const float* __restrict__ B) {
    __shared__ float As[16][256];
    int t = threadIdx.x;
    int i0 = blockIdx.x * 256;
    int o0 = blockIdx.y * 64;
#pragma unroll
    for (int r = 0; r < 16; r++)
        As[r][t] = A[r * 4096 + i0 + t];
    __syncthreads();
    for (int oo = 0; oo < 64; oo++) {
        int o = o0 + oo;
        const float* Br = B + o * 16;
        float s = 0.f;
#pragma unroll
        for (int r = 0; r < 16; r++) s += Br[r] * As[r][t];
        float v = W[((size_t)o << 12) + i0 + t] + 2.0f * s;
        g_Weff[((size_t)o << 12) + i0 + t] = __uint_as_float(f2tf32(v));
    }
}

// ---------------- main GEMM: mma.sync tf32 ----------------
// CTA 128x256x32, 16 warps in 4(M)x4(N), warp tile 32x64.
// 4-stage cp.async pipeline, ONE __syncthreads per K-iteration.
// A (= x) loaded raw; fragments rounded to tf32 in-register.
__global__ __launch_bounds__(NTHREADS, 1)
void lora_gemm_kernel(const float* __restrict__ x,
                      const float* __restrict__ bias, float* __restrict__ out) {
    extern __shared__ float smem[];
    uint32_t smem_base = smem_u32(smem);

    int tid = threadIdx.x;
    int wid = tid >> 5;
    int lane = tid & 31;
    int warp_m = (wid & 3) * 32;        // 0,32,64,96
    int warp_n = (wid >> 2) * 64;       // 0,64,128,192

    int m0 = blockIdx.y * BM;
    int n0 = blockIdx.x * BN;

    const float* gA = x + ((size_t)m0 << 12);
    const float* gB = g_Weff + ((size_t)n0 << 12);

    // one stage: A 128 rows x 32 cols (8 chunks of 16B), B 256 rows x 32 cols
    auto load_stage = [&](int stage, int kt) {
        uint32_t sA = smem_base + (uint32_t)(stage * STAGE_W * 4);
        uint32_t sB = sA + A_STAGE_W * 4;
        int kbase = kt << 5;   // kt*32
#pragma unroll
        for (int i = 0; i < 2; i++) {        // A: 128*8 = 1024 chunks / 512 thr
            int ch = tid + i * NTHREADS;
            int row = ch >> 3, c = ch & 7;
            CP_ASYNC16(sA + (uint32_t)(row * PAD_K + c * 4) * 4,
                       gA + (((size_t)row) << 12) + kbase + (c << 2));
        }
#pragma unroll
        for (int i = 0; i < 4; i++) {        // B: 256*8 = 2048 chunks
            int ch = tid + i * NTHREADS;
            int row = ch >> 3, c = ch & 7;
            CP_ASYNC16(sB + (uint32_t)(row * PAD_K + c * 4) * 4,
                       gB + (((size_t)row) << 12) + kbase + (c << 2));
        }
        CP_COMMIT();
    };

    float acc[2][8][4];
#pragma unroll
    for (int mt = 0; mt < 2; mt++)
#pragma unroll
        for (int nt = 0; nt < 8; nt++)
#pragma unroll
            for (int i = 0; i < 4; i++) acc[mt][nt][i] = 0.f;

    // prologue: fill stages 0..2 (3 groups in flight)
    load_stage(0, 0);
    load_stage(1, 1);
    load_stage(2, 2);

    int lr = lane >> 2;     // 0..7
    int lc = lane & 3;      // 0..3

    const uint32_t a_off = (uint32_t)(warp_m + lr) * PAD_K + lc;   // + mt*16*PAD_K + ks*8
    const uint32_t b_off = (uint32_t)(warp_n + lr) * PAD_K + lc;   // + nt*8*PAD_K  + ks*8

#pragma unroll 2
    for (int k = 0; k < NK; k++) {
        // exactly 3 groups outstanding here -> wait for tile k
        CP_WAIT(2);
        __syncthreads();

        // prefetch tile k+3 into slot (k+3)&3 == (k-1)&3 (consumed at iter k-1;
        // the barrier above covers the WAR hazard). Uniform group count.
        if (k + 3 < NK) load_stage((k + 3) & 3, k + 3);
        else            CP_COMMIT();

        const float* As = smem + (size_t)(k & 3) * STAGE_W + a_off;
        const float* Bs = smem + (size_t)(k & 3) * STAGE_W + A_STAGE_W + b_off;

#pragma unroll
        for (int ks = 0; ks < 4; ks++) {
            int kk = ks * 8;
            uint32_t af[2][4];
            uint32_t bf[8][2];
#pragma unroll
            for (int mt = 0; mt < 2; mt++) {
                const float* p = As + mt * 16 * PAD_K + kk;
                af[mt][0] = f2tf32(p[0]);               // round x -> tf32 in-register
                af[mt][1] = f2tf32(p[8 * PAD_K]);
                af[mt][2] = f2tf32(p[4]);
                af[mt][3] = f2tf32(p[8 * PAD_K + 4]);
            }
#pragma unroll
            for (int nt = 0; nt < 8; nt++) {
                const float* p = Bs + nt * 8 * PAD_K + kk;
                bf[nt][0] = __float_as_uint(p[0]);      // Weff pre-rounded
                bf[nt][1] = __float_as_uint(p[4]);
            }
#pragma unroll
            for (int mt = 0; mt < 2; mt++)
#pragma unroll
                for (int nt = 0; nt < 8; nt++)
                    mma_tf32(acc[mt][nt], af[mt], bf[nt]);
        }
        // no trailing barrier — next iteration's top barrier covers reuse.
    }

    // epilogue: direct stores + bias. c0,c1 -> (row, 2*lc+{0,1}); c2,c3 -> row+8.
#pragma unroll
    for (int nt = 0; nt < 8; nt++) {
        int col = n0 + warp_n + nt * 8 + 2 * lc;
        float bv0 = bias[col];
        float bv1 = bias[col + 1];
#pragma unroll
        for (int mt = 0; mt < 2; mt++) {
            int row = m0 + warp_m + mt * 16 + lr;
            float2 v0 = make_float2(acc[mt][nt][0] + bv0, acc[mt][nt][1] + bv1);
            float2 v1 = make_float2(acc[mt][nt][2] + bv0, acc[mt][nt][3] + bv1);
            *reinterpret_cast<float2*>(out + (((size_t)row) << 12) + col) = v0;
            *reinterpret_cast<float2*>(out + (((size_t)(row + 8)) << 12) + col) = v1;
        }
    }
}

// ---------------- launch ----------------
extern "C" void kernel_launch(void* const* d_in, const int* in_sizes, int n_in,
                              void* d_out, int out_size) {
    const float* x = (const float*)d_in[0];   // [8192, 4096]
    const float* W = (const float*)d_in[1];   // [4096, 4096]
    const float* b = (const float*)d_in[2];   // [4096]
    const float* A = (const float*)d_in[3];   // [16, 4096]
    const float* B = (const float*)d_in[4];   // [4096, 16]
    float* out = (float*)d_out;               // [8192, 4096]

    cudaFuncSetAttribute(lora_gemm_kernel,
                         cudaFuncAttributeMaxDynamicSharedMemorySize, SMEM_TOTAL);

    // 1) Weff = round_tf32(W + 2*B@A)
    weff_kernel<<<dim3(16, 64), 256>>>(W, A, B);
    // 2) out = round_tf32(x) @ Weff^T + b   (rounding fused into fragment loads)
    lora_gemm_kernel<<<dim3(N_DIM / BN, M_DIM / BM), NTHREADS, SMEM_TOTAL>>>(x, b, out);
}